// round 5
// baseline (speedup 1.0000x reference)
#include <cuda_runtime.h>
#include <cstdint>

typedef unsigned long long ull;

#define NN_MAX 100000
#define LDIM 64
#define HD 32
#define EDIM 4
#define NCOL 36   // 32 (W1) + 4 (W_direct) fused columns

// Scratch: u[node][j] = sum_{k<64} x[node][k] * [W1 | Wd][k][j]
__device__ __align__(16) float g_u[NN_MAX * NCOL];

__device__ __forceinline__ ull pack2(float a) {
    ull r; asm("mov.b64 %0, {%1, %1};" : "=l"(r) : "f"(a)); return r;
}
__device__ __forceinline__ ull fma2(ull a, ull b, ull c) {
    ull d; asm("fma.rn.f32x2 %0, %1, %2, %3;" : "=l"(d) : "l"(a), "l"(b), "l"(c)); return d;
}
__device__ __forceinline__ ull add2(ull a, ull b) {
    ull d; asm("add.rn.f32x2 %0, %1, %2;" : "=l"(d) : "l"(a), "l"(b)); return d;
}
__device__ __forceinline__ void unpack2(ull v, float& lo, float& hi) {
    asm("mov.b64 {%0, %1}, %2;" : "=f"(lo), "=f"(hi) : "l"(v));
}

// ---------------------------------------------------------------------------
// Kernel 1: per-node precompute u = x[:, :] @ [W1[:64] | Wd[:64]]
// ---------------------------------------------------------------------------
__global__ void __launch_bounds__(256) precompute_u(
    const float* __restrict__ x,
    const float* __restrict__ W1,
    const float* __restrict__ Wd,
    int n_nodes)
{
    __shared__ __align__(16) float sW[LDIM][NCOL];
    int tid = threadIdx.x;
    for (int i = tid; i < LDIM * NCOL; i += 256) {
        int k = i / NCOL, j = i - k * NCOL;
        sW[k][j] = (j < HD) ? W1[k * HD + j] : Wd[k * EDIM + (j - HD)];
    }
    __syncthreads();

    int node = blockIdx.x * 256 + tid;
    if (node >= n_nodes) return;

    float acc[NCOL];
    #pragma unroll
    for (int j = 0; j < NCOL; j++) acc[j] = 0.f;

    const float4* xr = (const float4*)(x + (size_t)node * LDIM);
    #pragma unroll 4
    for (int k4 = 0; k4 < LDIM / 4; k4++) {
        float4 v = __ldg(xr + k4);
        #pragma unroll
        for (int j = 0; j < NCOL; j++) {
            acc[j] = fmaf(v.x, sW[4 * k4 + 0][j], acc[j]);
            acc[j] = fmaf(v.y, sW[4 * k4 + 1][j], acc[j]);
            acc[j] = fmaf(v.z, sW[4 * k4 + 2][j], acc[j]);
            acc[j] = fmaf(v.w, sW[4 * k4 + 3][j], acc[j]);
        }
    }
    float4* ur = (float4*)(g_u + (size_t)node * NCOL);
    #pragma unroll
    for (int j4 = 0; j4 < NCOL / 4; j4++) {
        float4 r;
        r.x = acc[4 * j4 + 0]; r.y = acc[4 * j4 + 1];
        r.z = acc[4 * j4 + 2]; r.w = acc[4 * j4 + 3];
        ur[j4] = r;
    }
}

// ---------------------------------------------------------------------------
// Kernel 2: per-edge MLP.
//   a1 = u_s + u_t + max(x_s,x_t) @ Wdiff   (Wdiff = W[64:] - W[:64], 64x36)
//   h  = relu(a1[:32] + b1)
//   h2 = relu(h @ W2 + b2 + h)
//   out = h2 @ W3 + b3 + a1[32:36] + b_direct
// ---------------------------------------------------------------------------
__global__ void __launch_bounds__(256) edge_kernel(
    const float* __restrict__ x,
    const void* __restrict__ ei,
    const float* __restrict__ W1, const float* __restrict__ b1,
    const float* __restrict__ Wd, const float* __restrict__ bd,
    const float* __restrict__ W2, const float* __restrict__ b2,
    const float* __restrict__ W3, const float* __restrict__ b3,
    float* __restrict__ out, int n_edges, int n_nodes)
{
    __shared__ __align__(16) float sWdiff[LDIM][NCOL];  // 9216 B
    __shared__ __align__(16) float sW2[HD][HD];         // 4096 B
    __shared__ __align__(16) float sW3[HD][EDIM];       //  512 B
    __shared__ float sb1[HD], sb2[HD], sbo[EDIM];
    __shared__ int s_is64;

    int tid = threadIdx.x;
    if (tid == 0) {
        // dtype probe: int32 data read as int64 pairs gives values far outside
        // [0, n_nodes). Deterministic, identical in every block.
        const long long* p = (const long long*)ei;
        int ok = 1;
        for (int i = 0; i < 64; i++) {
            long long v = p[i];
            if (v < 0 || v >= n_nodes) { ok = 0; break; }
        }
        s_is64 = ok;
    }
    for (int i = tid; i < LDIM * NCOL; i += 256) {
        int k = i / NCOL, j = i - k * NCOL;
        float hi, lo;
        if (j < HD) { hi = W1[(LDIM + k) * HD + j];        lo = W1[k * HD + j]; }
        else        { hi = Wd[(LDIM + k) * EDIM + (j-HD)]; lo = Wd[k * EDIM + (j-HD)]; }
        sWdiff[k][j] = hi - lo;
    }
    for (int i = tid; i < HD * HD; i += 256)  (&sW2[0][0])[i] = W2[i];
    for (int i = tid; i < HD * EDIM; i += 256)(&sW3[0][0])[i] = W3[i];
    if (tid < HD)  { sb1[tid] = b1[tid]; sb2[tid] = b2[tid]; }
    if (tid < EDIM) sbo[tid] = b3[tid] + bd[tid];
    __syncthreads();

    int e = blockIdx.x * 256 + tid;
    if (e >= n_edges) return;

    // ---- index load: dtype-flexible, clamped (never IMA) ----
    unsigned s, t;
    if (s_is64) {
        s = (unsigned)((const long long*)ei)[e];
        t = (unsigned)((const long long*)ei)[(size_t)n_edges + e];
    } else {
        s = (unsigned)((const int*)ei)[e];
        t = (unsigned)((const int*)ei)[(size_t)n_edges + e];
    }
    unsigned nm1 = (unsigned)(n_nodes - 1);
    s = (s < nm1) ? s : nm1;
    t = (t < nm1) ? t : nm1;

    // ---- GEMM1: max(xs,xt) @ Wdiff, packed f32x2 accumulators, pipelined ----
    ull acc[NCOL / 2];
    #pragma unroll
    for (int i = 0; i < NCOL / 2; i++) acc[i] = 0ULL;

    const float4* xs = (const float4*)(x + (size_t)s * LDIM);
    const float4* xt = (const float4*)(x + (size_t)t * LDIM);

    float4 ca = __ldg(xs);
    float4 cb = __ldg(xt);
    #pragma unroll 4
    for (int k4 = 0; k4 < LDIM / 4; k4++) {
        float4 na, nb;
        if (k4 + 1 < LDIM / 4) { na = __ldg(xs + k4 + 1); nb = __ldg(xt + k4 + 1); }
        float m[4];
        m[0] = fmaxf(ca.x, cb.x); m[1] = fmaxf(ca.y, cb.y);
        m[2] = fmaxf(ca.z, cb.z); m[3] = fmaxf(ca.w, cb.w);
        #pragma unroll
        for (int kk = 0; kk < 4; kk++) {
            ull mm = pack2(m[kk]);
            const ulonglong2* wr = (const ulonglong2*)(&sWdiff[k4 * 4 + kk][0]);
            #pragma unroll
            for (int j4 = 0; j4 < NCOL / 4; j4++) {
                ulonglong2 w = wr[j4];
                acc[2 * j4 + 0] = fma2(mm, w.x, acc[2 * j4 + 0]);
                acc[2 * j4 + 1] = fma2(mm, w.y, acc[2 * j4 + 1]);
            }
        }
        ca = na; cb = nb;
    }

    // add u_s + u_t directly into packed accumulators (u rows are f32x2 pairs)
    const ulonglong2* us2 = (const ulonglong2*)(g_u + (size_t)s * NCOL);
    const ulonglong2* ut2 = (const ulonglong2*)(g_u + (size_t)t * NCOL);
    #pragma unroll
    for (int j4 = 0; j4 < NCOL / 4; j4++) {
        ulonglong2 uu = __ldg(us2 + j4);
        ulonglong2 vv = __ldg(ut2 + j4);
        acc[2 * j4 + 0] = add2(acc[2 * j4 + 0], add2(uu.x, vv.x));
        acc[2 * j4 + 1] = add2(acc[2 * j4 + 1], add2(uu.y, vv.y));
    }

    // unpack -> h (bias+relu fused) and cd (direct path, cols 32..35)
    float h[HD], cd[EDIM];
    #pragma unroll
    for (int i = 0; i < HD / 2; i++) {
        float lo, hi; unpack2(acc[i], lo, hi);
        h[2 * i + 0] = fmaxf(lo + sb1[2 * i + 0], 0.f);
        h[2 * i + 1] = fmaxf(hi + sb1[2 * i + 1], 0.f);
    }
    unpack2(acc[16], cd[0], cd[1]);
    unpack2(acc[17], cd[2], cd[3]);

    // ---- GEMM2: h @ W2, residual + relu ----
    ull acc2[HD / 2];
    #pragma unroll
    for (int i = 0; i < HD / 2; i++) acc2[i] = 0ULL;
    #pragma unroll 8
    for (int k = 0; k < HD; k++) {
        ull hk = pack2(h[k]);
        const ulonglong2* wr = (const ulonglong2*)(&sW2[k][0]);
        #pragma unroll
        for (int j4 = 0; j4 < HD / 4; j4++) {
            ulonglong2 w = wr[j4];
            acc2[2 * j4 + 0] = fma2(hk, w.x, acc2[2 * j4 + 0]);
            acc2[2 * j4 + 1] = fma2(hk, w.y, acc2[2 * j4 + 1]);
        }
    }
    float h2[HD];
    #pragma unroll
    for (int i = 0; i < HD / 2; i++) {
        float lo, hi; unpack2(acc2[i], lo, hi);
        h2[2 * i + 0] = fmaxf(lo + sb2[2 * i + 0] + h[2 * i + 0], 0.f);
        h2[2 * i + 1] = fmaxf(hi + sb2[2 * i + 1] + h[2 * i + 1], 0.f);
    }

    // ---- GEMM3: h2 @ W3 ----
    ull o01 = 0ULL, o23 = 0ULL;
    #pragma unroll 8
    for (int k = 0; k < HD; k++) {
        ull hk = pack2(h2[k]);
        ulonglong2 w = *(const ulonglong2*)(&sW3[k][0]);
        o01 = fma2(hk, w.x, o01);
        o23 = fma2(hk, w.y, o23);
    }
    float o0, o1, o2, o3;
    unpack2(o01, o0, o1);
    unpack2(o23, o2, o3);

    float4 r;
    r.x = o0 + cd[0] + sbo[0];
    r.y = o1 + cd[1] + sbo[1];
    r.z = o2 + cd[2] + sbo[2];
    r.w = o3 + cd[3] + sbo[3];
    ((float4*)out)[e] = r;
}

// ---------------------------------------------------------------------------
extern "C" void kernel_launch(void* const* d_in, const int* in_sizes, int n_in,
                              void* d_out, int out_size) {
    const float* x  = (const float*)d_in[0];
    const void*  ei = d_in[1];
    const float* Wd = (const float*)d_in[2];
    const float* bd = (const float*)d_in[3];
    const float* W1 = (const float*)d_in[4];
    const float* b1 = (const float*)d_in[5];
    const float* W2 = (const float*)d_in[6];
    const float* b2 = (const float*)d_in[7];
    const float* W3 = (const float*)d_in[8];
    const float* b3 = (const float*)d_in[9];
    float* out = (float*)d_out;

    int n_nodes = in_sizes[0] / LDIM;
    if (n_nodes > NN_MAX) n_nodes = NN_MAX;
    int n_edges = in_sizes[1] / 2;

    precompute_u<<<(n_nodes + 255) / 256, 256>>>(x, W1, Wd, n_nodes);
    edge_kernel<<<(n_edges + 255) / 256, 256>>>(x, ei, W1, b1, Wd, bd,
                                                W2, b2, W3, b3, out, n_edges, n_nodes);
}

// round 6
// speedup vs baseline: 1.0243x; 1.0243x over previous
#include <cuda_runtime.h>
#include <cstdint>

typedef unsigned long long ull;

#define NN_MAX 100000
#define LDIM 64
#define HD 32
#define EDIM 4
#define NCOL 36   // 32 (W1) + 4 (W_direct) fused columns

// dynamic smem layout (float offsets)
#define W_OFF_WDIFF 0
#define W_OFF_W2    2304
#define W_OFF_W3    3328
#define W_OFF_B1    3456
#define W_OFF_B2    3488
#define W_OFF_BO    3520
#define TILE_OFF    3536
#define M_STRIDE    68                       // 64 + 4 pad (bank-conflict-free)
#define PER_WARP    (32 * M_STRIDE + 32 * NCOL)   // 2176 + 1152 = 3328
#define SMEM_FLOATS (TILE_OFF + 4 * PER_WARP)     // 16848
#define SMEM_BYTES  (SMEM_FLOATS * 4)             // 67392

// Scratch: u[node][j] = sum_{k<64} x[node][k] * [W1 | Wd][k][j]
__device__ __align__(16) float g_u[NN_MAX * NCOL];

__device__ __forceinline__ ull pack2(float a) {
    ull r; asm("mov.b64 %0, {%1, %1};" : "=l"(r) : "f"(a)); return r;
}
__device__ __forceinline__ ull fma2(ull a, ull b, ull c) {
    ull d; asm("fma.rn.f32x2 %0, %1, %2, %3;" : "=l"(d) : "l"(a), "l"(b), "l"(c)); return d;
}
__device__ __forceinline__ ull add2(ull a, ull b) {
    ull d; asm("add.rn.f32x2 %0, %1, %2;" : "=l"(d) : "l"(a), "l"(b)); return d;
}
__device__ __forceinline__ void unpack2(ull v, float& lo, float& hi) {
    asm("mov.b64 {%0, %1}, %2;" : "=f"(lo), "=f"(hi) : "l"(v));
}

// ---------------------------------------------------------------------------
// Kernel 1: per-node precompute u = x[:, :] @ [W1[:64] | Wd[:64]]
// ---------------------------------------------------------------------------
__global__ void __launch_bounds__(256) precompute_u(
    const float* __restrict__ x,
    const float* __restrict__ W1,
    const float* __restrict__ Wd,
    int n_nodes)
{
    __shared__ __align__(16) float sW[LDIM][NCOL];
    int tid = threadIdx.x;
    for (int i = tid; i < LDIM * NCOL; i += 256) {
        int k = i / NCOL, j = i - k * NCOL;
        sW[k][j] = (j < HD) ? W1[k * HD + j] : Wd[k * EDIM + (j - HD)];
    }
    __syncthreads();

    int node = blockIdx.x * 256 + tid;
    if (node >= n_nodes) return;

    float acc[NCOL];
    #pragma unroll
    for (int j = 0; j < NCOL; j++) acc[j] = 0.f;

    const float4* xr = (const float4*)(x + (size_t)node * LDIM);
    #pragma unroll 4
    for (int k4 = 0; k4 < LDIM / 4; k4++) {
        float4 v = __ldg(xr + k4);
        #pragma unroll
        for (int j = 0; j < NCOL; j++) {
            acc[j] = fmaf(v.x, sW[4 * k4 + 0][j], acc[j]);
            acc[j] = fmaf(v.y, sW[4 * k4 + 1][j], acc[j]);
            acc[j] = fmaf(v.z, sW[4 * k4 + 2][j], acc[j]);
            acc[j] = fmaf(v.w, sW[4 * k4 + 3][j], acc[j]);
        }
    }
    float4* ur = (float4*)(g_u + (size_t)node * NCOL);
    #pragma unroll
    for (int j4 = 0; j4 < NCOL / 4; j4++) {
        float4 r;
        r.x = acc[4 * j4 + 0]; r.y = acc[4 * j4 + 1];
        r.z = acc[4 * j4 + 2]; r.w = acc[4 * j4 + 3];
        ur[j4] = r;
    }
}

// ---------------------------------------------------------------------------
// Kernel 2: warp-cooperative two-phase edge MLP.
// Phase A: coalesced gather of x rows (max) and g_u rows (sum) into smem.
// Phase B: per-thread packed-f32x2 MLP from smem tiles.
// ---------------------------------------------------------------------------
__global__ void __launch_bounds__(128) edge_kernel(
    const float* __restrict__ x,
    const void* __restrict__ ei,
    const float* __restrict__ W1, const float* __restrict__ b1,
    const float* __restrict__ Wd, const float* __restrict__ bd,
    const float* __restrict__ W2, const float* __restrict__ b2,
    const float* __restrict__ W3, const float* __restrict__ b3,
    float* __restrict__ out, int n_edges, int n_nodes)
{
    extern __shared__ __align__(16) float dsm[];
    __shared__ int s_is64;

    int tid = threadIdx.x;
    if (tid == 0) {
        // dtype probe: int32 data read as int64 pairs gives values far outside
        // [0, n_nodes). Deterministic, identical in every block.
        const long long* p = (const long long*)ei;
        int ok = 1;
        for (int i = 0; i < 64; i++) {
            long long v = p[i];
            if (v < 0 || v >= n_nodes) { ok = 0; break; }
        }
        s_is64 = ok;
    }
    // weights -> dynamic smem (whole block participates)
    for (int i = tid; i < LDIM * NCOL; i += 128) {
        int k = i / NCOL, j = i - k * NCOL;
        float hi, lo;
        if (j < HD) { hi = W1[(LDIM + k) * HD + j];        lo = W1[k * HD + j]; }
        else        { hi = Wd[(LDIM + k) * EDIM + (j-HD)]; lo = Wd[k * EDIM + (j-HD)]; }
        dsm[W_OFF_WDIFF + i] = hi - lo;
    }
    for (int i = tid; i < HD * HD; i += 128)   dsm[W_OFF_W2 + i] = W2[i];
    for (int i = tid; i < HD * EDIM; i += 128) dsm[W_OFF_W3 + i] = W3[i];
    if (tid < HD)  { dsm[W_OFF_B1 + tid] = b1[tid]; dsm[W_OFF_B2 + tid] = b2[tid]; }
    if (tid < EDIM) dsm[W_OFF_BO + tid] = b3[tid] + bd[tid];
    __syncthreads();

    int warp = tid >> 5, lane = tid & 31;
    int tile_base = (blockIdx.x * 4 + warp) * 32;
    if (tile_base >= n_edges) return;

    int e  = tile_base + lane;
    int ec = (e < n_edges) ? e : (n_edges - 1);

    // ---- index load: dtype-flexible, clamped (never IMA) ----
    unsigned s, t;
    if (s_is64) {
        s = (unsigned)((const long long*)ei)[ec];
        t = (unsigned)((const long long*)ei)[(size_t)n_edges + ec];
    } else {
        s = (unsigned)((const int*)ei)[ec];
        t = (unsigned)((const int*)ei)[(size_t)n_edges + ec];
    }
    unsigned nm1 = (unsigned)(n_nodes - 1);
    s = (s < nm1) ? s : nm1;
    t = (t < nm1) ? t : nm1;

    float* sm_m = dsm + TILE_OFF + warp * PER_WARP;       // [32][M_STRIDE]
    float* sm_u = sm_m + 32 * M_STRIDE;                   // [32][NCOL]

    // ================= Phase A: cooperative gather =================
    int half = lane >> 4, li = lane & 15;
    const unsigned FULL = 0xffffffffu;
    #pragma unroll 4
    for (int ee = 0; ee < 32; ee++) {
        unsigned sr = __shfl_sync(FULL, s, ee);
        unsigned tr = __shfl_sync(FULL, t, ee);
        unsigned row = half ? tr : sr;

        // x row: lanes 0-15 cover 64 floats of row_s, 16-31 of row_t
        const float4* px = (const float4*)(x + (size_t)row * LDIM);
        float4 v = __ldg(px + li);
        float4 m;
        m.x = fmaxf(v.x, __shfl_xor_sync(FULL, v.x, 16));
        m.y = fmaxf(v.y, __shfl_xor_sync(FULL, v.y, 16));
        m.z = fmaxf(v.z, __shfl_xor_sync(FULL, v.z, 16));
        m.w = fmaxf(v.w, __shfl_xor_sync(FULL, v.w, 16));
        if (lane < 16) *(float4*)(sm_m + ee * M_STRIDE + li * 4) = m;

        // u row: 36 floats = 9 float4 chunks; lanes 0-8 (s) / 16-24 (t)
        const float4* pu = (const float4*)(g_u + (size_t)row * NCOL);
        int uli = (li < 9) ? li : 8;
        float4 uv = __ldg(pu + uli);
        float4 us;
        us.x = uv.x + __shfl_xor_sync(FULL, uv.x, 16);
        us.y = uv.y + __shfl_xor_sync(FULL, uv.y, 16);
        us.z = uv.z + __shfl_xor_sync(FULL, uv.z, 16);
        us.w = uv.w + __shfl_xor_sync(FULL, uv.w, 16);
        if (lane < 9) *(float4*)(sm_u + ee * NCOL + li * 4) = us;
    }
    __syncwarp();

    // ================= Phase B: per-thread MLP from smem =================
    ull acc[NCOL / 2];
    #pragma unroll
    for (int i = 0; i < NCOL / 2; i++) acc[i] = 0ULL;

    const float* mrow = sm_m + lane * M_STRIDE;
    #pragma unroll
    for (int k4 = 0; k4 < LDIM / 4; k4++) {
        float4 mv = *(const float4*)(mrow + k4 * 4);
        float mm4[4] = {mv.x, mv.y, mv.z, mv.w};
        #pragma unroll
        for (int kk = 0; kk < 4; kk++) {
            ull mm = pack2(mm4[kk]);
            const ulonglong2* wr =
                (const ulonglong2*)(dsm + W_OFF_WDIFF + (k4 * 4 + kk) * NCOL);
            #pragma unroll
            for (int j4 = 0; j4 < NCOL / 4; j4++) {
                ulonglong2 w = wr[j4];
                acc[2 * j4 + 0] = fma2(mm, w.x, acc[2 * j4 + 0]);
                acc[2 * j4 + 1] = fma2(mm, w.y, acc[2 * j4 + 1]);
            }
        }
    }

    // add presummed u_s + u_t
    const ulonglong2* uu = (const ulonglong2*)(sm_u + lane * NCOL);
    #pragma unroll
    for (int j4 = 0; j4 < NCOL / 4; j4++) {
        ulonglong2 w = uu[j4];
        acc[2 * j4 + 0] = add2(acc[2 * j4 + 0], w.x);
        acc[2 * j4 + 1] = add2(acc[2 * j4 + 1], w.y);
    }

    // unpack -> h (bias+relu fused) and cd (direct path, cols 32..35)
    float h[HD], cd[EDIM];
    #pragma unroll
    for (int i = 0; i < HD / 2; i++) {
        float lo, hi; unpack2(acc[i], lo, hi);
        h[2 * i + 0] = fmaxf(lo + dsm[W_OFF_B1 + 2 * i + 0], 0.f);
        h[2 * i + 1] = fmaxf(hi + dsm[W_OFF_B1 + 2 * i + 1], 0.f);
    }
    unpack2(acc[16], cd[0], cd[1]);
    unpack2(acc[17], cd[2], cd[3]);

    // ---- GEMM2: h @ W2, residual + relu ----
    ull acc2[HD / 2];
    #pragma unroll
    for (int i = 0; i < HD / 2; i++) acc2[i] = 0ULL;
    #pragma unroll 8
    for (int k = 0; k < HD; k++) {
        ull hk = pack2(h[k]);
        const ulonglong2* wr = (const ulonglong2*)(dsm + W_OFF_W2 + k * HD);
        #pragma unroll
        for (int j4 = 0; j4 < HD / 4; j4++) {
            ulonglong2 w = wr[j4];
            acc2[2 * j4 + 0] = fma2(hk, w.x, acc2[2 * j4 + 0]);
            acc2[2 * j4 + 1] = fma2(hk, w.y, acc2[2 * j4 + 1]);
        }
    }
    float h2[HD];
    #pragma unroll
    for (int i = 0; i < HD / 2; i++) {
        float lo, hi; unpack2(acc2[i], lo, hi);
        h2[2 * i + 0] = fmaxf(lo + dsm[W_OFF_B2 + 2 * i + 0] + h[2 * i + 0], 0.f);
        h2[2 * i + 1] = fmaxf(hi + dsm[W_OFF_B2 + 2 * i + 1] + h[2 * i + 1], 0.f);
    }

    // ---- GEMM3: h2 @ W3 ----
    ull o01 = 0ULL, o23 = 0ULL;
    #pragma unroll 8
    for (int k = 0; k < HD; k++) {
        ull hk = pack2(h2[k]);
        ulonglong2 w = *(const ulonglong2*)(dsm + W_OFF_W3 + k * EDIM);
        o01 = fma2(hk, w.x, o01);
        o23 = fma2(hk, w.y, o23);
    }
    float o0, o1, o2, o3;
    unpack2(o01, o0, o1);
    unpack2(o23, o2, o3);

    if (e < n_edges) {
        float4 r;
        r.x = o0 + cd[0] + dsm[W_OFF_BO + 0];
        r.y = o1 + cd[1] + dsm[W_OFF_BO + 1];
        r.z = o2 + cd[2] + dsm[W_OFF_BO + 2];
        r.w = o3 + cd[3] + dsm[W_OFF_BO + 3];
        ((float4*)out)[e] = r;
    }
}

// ---------------------------------------------------------------------------
extern "C" void kernel_launch(void* const* d_in, const int* in_sizes, int n_in,
                              void* d_out, int out_size) {
    const float* x  = (const float*)d_in[0];
    const void*  ei = d_in[1];
    const float* Wd = (const float*)d_in[2];
    const float* bd = (const float*)d_in[3];
    const float* W1 = (const float*)d_in[4];
    const float* b1 = (const float*)d_in[5];
    const float* W2 = (const float*)d_in[6];
    const float* b2 = (const float*)d_in[7];
    const float* W3 = (const float*)d_in[8];
    const float* b3 = (const float*)d_in[9];
    float* out = (float*)d_out;

    int n_nodes = in_sizes[0] / LDIM;
    if (n_nodes > NN_MAX) n_nodes = NN_MAX;
    int n_edges = in_sizes[1] / 2;

    static int attr_done = 0;
    if (!attr_done) {
        cudaFuncSetAttribute(edge_kernel,
                             cudaFuncAttributeMaxDynamicSharedMemorySize,
                             SMEM_BYTES);
        attr_done = 1;
    }

    precompute_u<<<(n_nodes + 255) / 256, 256>>>(x, W1, Wd, n_nodes);

    int tiles  = (n_edges + 31) / 32;
    int blocks = (tiles + 3) / 4;
    edge_kernel<<<blocks, 128, SMEM_BYTES>>>(x, ei, W1, b1, Wd, bd,
                                             W2, b2, W3, b3, out, n_edges, n_nodes);
}

// round 7
// speedup vs baseline: 1.1519x; 1.1246x over previous
#include <cuda_runtime.h>
#include <cstdint>

typedef unsigned long long ull;

#define NN_MAX 100000
#define LDIM 64
#define HD 32
#define EDIM 4
#define NCOL 36   // 32 (W1) + 4 (W_direct) fused columns

// dynamic smem layout (float offsets)
#define W_OFF_WDIFF 0
#define W_OFF_W2    2304
#define W_OFF_W3    3328
#define W_OFF_B1    3456
#define W_OFF_B2    3488
#define W_OFF_BO    3520
#define TILE_OFF    3536
#define M_STRIDE    68                        // 17 float4s (odd) -> conflict-free
#define EPW         64                        // edges per warp (EPT=2)
#define PER_WARP    (EPW * M_STRIDE + EPW * NCOL)   // 4352 + 2304 = 6656
#define NWARPS      8
#define SMEM_FLOATS (TILE_OFF + NWARPS * PER_WARP)  // 3536 + 53248 = 56784
#define SMEM_BYTES  (SMEM_FLOATS * 4)               // 227136 (< 232448 cap)

// Scratch: u[node][j] = sum_{k<64} x[node][k] * [W1 | Wd][k][j]
__device__ __align__(16) float g_u[NN_MAX * NCOL];

__device__ __forceinline__ ull pack2(float a) {
    ull r; asm("mov.b64 %0, {%1, %1};" : "=l"(r) : "f"(a)); return r;
}
__device__ __forceinline__ ull fma2(ull a, ull b, ull c) {
    ull d; asm("fma.rn.f32x2 %0, %1, %2, %3;" : "=l"(d) : "l"(a), "l"(b), "l"(c)); return d;
}
__device__ __forceinline__ ull add2(ull a, ull b) {
    ull d; asm("add.rn.f32x2 %0, %1, %2;" : "=l"(d) : "l"(a), "l"(b)); return d;
}
__device__ __forceinline__ void unpack2(ull v, float& lo, float& hi) {
    asm("mov.b64 {%0, %1}, %2;" : "=f"(lo), "=f"(hi) : "l"(v));
}

// ---------------------------------------------------------------------------
// Kernel 1: per-node precompute u = x[:, :] @ [W1[:64] | Wd[:64]]
// ---------------------------------------------------------------------------
__global__ void __launch_bounds__(256) precompute_u(
    const float* __restrict__ x,
    const float* __restrict__ W1,
    const float* __restrict__ Wd,
    int n_nodes)
{
    __shared__ __align__(16) float sW[LDIM][NCOL];
    int tid = threadIdx.x;
    for (int i = tid; i < LDIM * NCOL; i += 256) {
        int k = i / NCOL, j = i - k * NCOL;
        sW[k][j] = (j < HD) ? W1[k * HD + j] : Wd[k * EDIM + (j - HD)];
    }
    __syncthreads();

    int node = blockIdx.x * 256 + tid;
    if (node >= n_nodes) return;

    float acc[NCOL];
    #pragma unroll
    for (int j = 0; j < NCOL; j++) acc[j] = 0.f;

    const float4* xr = (const float4*)(x + (size_t)node * LDIM);
    #pragma unroll 4
    for (int k4 = 0; k4 < LDIM / 4; k4++) {
        float4 v = __ldg(xr + k4);
        #pragma unroll
        for (int j = 0; j < NCOL; j++) {
            acc[j] = fmaf(v.x, sW[4 * k4 + 0][j], acc[j]);
            acc[j] = fmaf(v.y, sW[4 * k4 + 1][j], acc[j]);
            acc[j] = fmaf(v.z, sW[4 * k4 + 2][j], acc[j]);
            acc[j] = fmaf(v.w, sW[4 * k4 + 3][j], acc[j]);
        }
    }
    float4* ur = (float4*)(g_u + (size_t)node * NCOL);
    #pragma unroll
    for (int j4 = 0; j4 < NCOL / 4; j4++) {
        float4 r;
        r.x = acc[4 * j4 + 0]; r.y = acc[4 * j4 + 1];
        r.z = acc[4 * j4 + 2]; r.w = acc[4 * j4 + 3];
        ur[j4] = r;
    }
}

// ---------------------------------------------------------------------------
// Kernel 2: warp-cooperative two-phase edge MLP, 2 edges per thread.
// Phase A: coalesced gather of 64 x-row maxes and 64 u-row sums into smem.
// Phase B: per-thread packed-f32x2 MLP for 2 edges; every broadcast weight
//          load amortizes over both edges.
// ---------------------------------------------------------------------------
__global__ void __launch_bounds__(256) edge_kernel(
    const float* __restrict__ x,
    const void* __restrict__ ei,
    const float* __restrict__ W1, const float* __restrict__ b1,
    const float* __restrict__ Wd, const float* __restrict__ bd,
    const float* __restrict__ W2, const float* __restrict__ b2,
    const float* __restrict__ W3, const float* __restrict__ b3,
    float* __restrict__ out, int n_edges, int n_nodes)
{
    extern __shared__ __align__(16) float dsm[];
    __shared__ int s_is64;

    int tid = threadIdx.x;
    if (tid == 0) {
        // dtype probe: int32 data read as int64 pairs gives values far outside
        // [0, n_nodes). Deterministic, identical in every block.
        const long long* p = (const long long*)ei;
        int ok = 1;
        for (int i = 0; i < 64; i++) {
            long long v = p[i];
            if (v < 0 || v >= n_nodes) { ok = 0; break; }
        }
        s_is64 = ok;
    }
    // weights -> dynamic smem (whole block participates)
    for (int i = tid; i < LDIM * NCOL; i += 256) {
        int k = i / NCOL, j = i - k * NCOL;
        float hi, lo;
        if (j < HD) { hi = W1[(LDIM + k) * HD + j];        lo = W1[k * HD + j]; }
        else        { hi = Wd[(LDIM + k) * EDIM + (j-HD)]; lo = Wd[k * EDIM + (j-HD)]; }
        dsm[W_OFF_WDIFF + i] = hi - lo;
    }
    for (int i = tid; i < HD * HD; i += 256)   dsm[W_OFF_W2 + i] = W2[i];
    for (int i = tid; i < HD * EDIM; i += 256) dsm[W_OFF_W3 + i] = W3[i];
    if (tid < HD)  { dsm[W_OFF_B1 + tid] = b1[tid]; dsm[W_OFF_B2 + tid] = b2[tid]; }
    if (tid < EDIM) dsm[W_OFF_BO + tid] = b3[tid] + bd[tid];
    __syncthreads();

    int warp = tid >> 5, lane = tid & 31;
    int tile_base = (blockIdx.x * NWARPS + warp) * EPW;
    if (tile_base >= n_edges) return;

    int e0 = tile_base + lane;
    int e1 = e0 + 32;
    int ec0 = (e0 < n_edges) ? e0 : (n_edges - 1);
    int ec1 = (e1 < n_edges) ? e1 : (n_edges - 1);

    // ---- index loads: dtype-flexible, clamped (never IMA) ----
    unsigned s0, t0, s1, t1;
    if (s_is64) {
        s0 = (unsigned)((const long long*)ei)[ec0];
        t0 = (unsigned)((const long long*)ei)[(size_t)n_edges + ec0];
        s1 = (unsigned)((const long long*)ei)[ec1];
        t1 = (unsigned)((const long long*)ei)[(size_t)n_edges + ec1];
    } else {
        s0 = (unsigned)((const int*)ei)[ec0];
        t0 = (unsigned)((const int*)ei)[(size_t)n_edges + ec0];
        s1 = (unsigned)((const int*)ei)[ec1];
        t1 = (unsigned)((const int*)ei)[(size_t)n_edges + ec1];
    }
    unsigned nm1 = (unsigned)(n_nodes - 1);
    s0 = (s0 < nm1) ? s0 : nm1;  t0 = (t0 < nm1) ? t0 : nm1;
    s1 = (s1 < nm1) ? s1 : nm1;  t1 = (t1 < nm1) ? t1 : nm1;

    float* sm_m = dsm + TILE_OFF + warp * PER_WARP;     // [64][M_STRIDE]
    float* sm_u = sm_m + EPW * M_STRIDE;                // [64][NCOL]

    // ================= Phase A: cooperative gather (64 edges) =================
    int li = lane & 15;
    const unsigned FULL = 0xffffffffu;
    #pragma unroll 4
    for (int ee = 0; ee < EPW; ee++) {
        unsigned ssel = (ee < 32) ? s0 : s1;
        unsigned tsel = (ee < 32) ? t0 : t1;
        unsigned sr = __shfl_sync(FULL, ssel, ee & 31);
        unsigned tr = __shfl_sync(FULL, tsel, ee & 31);
        unsigned row = (lane >= 16) ? tr : sr;

        // x row: lanes 0-15 cover 64 floats of row_s, 16-31 of row_t
        const float4* px = (const float4*)(x + (size_t)row * LDIM);
        float4 v = __ldg(px + li);
        float4 m;
        m.x = fmaxf(v.x, __shfl_xor_sync(FULL, v.x, 16));
        m.y = fmaxf(v.y, __shfl_xor_sync(FULL, v.y, 16));
        m.z = fmaxf(v.z, __shfl_xor_sync(FULL, v.z, 16));
        m.w = fmaxf(v.w, __shfl_xor_sync(FULL, v.w, 16));
        if (lane < 16) *(float4*)(sm_m + ee * M_STRIDE + li * 4) = m;

        // u row: 36 floats = 9 float4 chunks; lanes 0-8 (s) / 16-24 (t)
        const float4* pu = (const float4*)(g_u + (size_t)row * NCOL);
        int uli = (li < 9) ? li : 8;
        float4 uv = __ldg(pu + uli);
        float4 us;
        us.x = uv.x + __shfl_xor_sync(FULL, uv.x, 16);
        us.y = uv.y + __shfl_xor_sync(FULL, uv.y, 16);
        us.z = uv.z + __shfl_xor_sync(FULL, uv.z, 16);
        us.w = uv.w + __shfl_xor_sync(FULL, uv.w, 16);
        if (lane < 9) *(float4*)(sm_u + ee * NCOL + li * 4) = us;
    }
    __syncwarp();

    // ================= Phase B: 2 edges per thread =================
    ull acc0[NCOL / 2], acc1[NCOL / 2];
    #pragma unroll
    for (int i = 0; i < NCOL / 2; i++) { acc0[i] = 0ULL; acc1[i] = 0ULL; }

    const float* mrow0 = sm_m + lane * M_STRIDE;
    const float* mrow1 = sm_m + (lane + 32) * M_STRIDE;
    #pragma unroll 4
    for (int k4 = 0; k4 < LDIM / 4; k4++) {
        float4 mv0 = *(const float4*)(mrow0 + k4 * 4);
        float4 mv1 = *(const float4*)(mrow1 + k4 * 4);
        float a4[4] = {mv0.x, mv0.y, mv0.z, mv0.w};
        float b4[4] = {mv1.x, mv1.y, mv1.z, mv1.w};
        #pragma unroll
        for (int kk = 0; kk < 4; kk++) {
            ull ma = pack2(a4[kk]);
            ull mb = pack2(b4[kk]);
            const ulonglong2* wr =
                (const ulonglong2*)(dsm + W_OFF_WDIFF + (k4 * 4 + kk) * NCOL);
            #pragma unroll
            for (int j4 = 0; j4 < NCOL / 4; j4++) {
                ulonglong2 w = wr[j4];
                acc0[2 * j4 + 0] = fma2(ma, w.x, acc0[2 * j4 + 0]);
                acc0[2 * j4 + 1] = fma2(ma, w.y, acc0[2 * j4 + 1]);
                acc1[2 * j4 + 0] = fma2(mb, w.x, acc1[2 * j4 + 0]);
                acc1[2 * j4 + 1] = fma2(mb, w.y, acc1[2 * j4 + 1]);
            }
        }
    }

    // add presummed u_s + u_t
    const ulonglong2* uu0 = (const ulonglong2*)(sm_u + lane * NCOL);
    const ulonglong2* uu1 = (const ulonglong2*)(sm_u + (lane + 32) * NCOL);
    #pragma unroll
    for (int j4 = 0; j4 < NCOL / 4; j4++) {
        ulonglong2 w0 = uu0[j4];
        ulonglong2 w1 = uu1[j4];
        acc0[2 * j4 + 0] = add2(acc0[2 * j4 + 0], w0.x);
        acc0[2 * j4 + 1] = add2(acc0[2 * j4 + 1], w0.y);
        acc1[2 * j4 + 0] = add2(acc1[2 * j4 + 0], w1.x);
        acc1[2 * j4 + 1] = add2(acc1[2 * j4 + 1], w1.y);
    }

    // unpack -> h (bias+relu fused) and cd (direct path, cols 32..35)
    float h0[HD], h1[HD], cd0[EDIM], cd1[EDIM];
    #pragma unroll
    for (int i = 0; i < HD / 2; i++) {
        float blo = dsm[W_OFF_B1 + 2 * i + 0];
        float bhi = dsm[W_OFF_B1 + 2 * i + 1];
        float lo, hi;
        unpack2(acc0[i], lo, hi);
        h0[2 * i + 0] = fmaxf(lo + blo, 0.f);
        h0[2 * i + 1] = fmaxf(hi + bhi, 0.f);
        unpack2(acc1[i], lo, hi);
        h1[2 * i + 0] = fmaxf(lo + blo, 0.f);
        h1[2 * i + 1] = fmaxf(hi + bhi, 0.f);
    }
    unpack2(acc0[16], cd0[0], cd0[1]);
    unpack2(acc0[17], cd0[2], cd0[3]);
    unpack2(acc1[16], cd1[0], cd1[1]);
    unpack2(acc1[17], cd1[2], cd1[3]);

    // ---- GEMM2: h @ W2, residual + relu ----
    ull acc2_0[HD / 2], acc2_1[HD / 2];
    #pragma unroll
    for (int i = 0; i < HD / 2; i++) { acc2_0[i] = 0ULL; acc2_1[i] = 0ULL; }
    #pragma unroll 8
    for (int k = 0; k < HD; k++) {
        ull hk0 = pack2(h0[k]);
        ull hk1 = pack2(h1[k]);
        const ulonglong2* wr = (const ulonglong2*)(dsm + W_OFF_W2 + k * HD);
        #pragma unroll
        for (int j4 = 0; j4 < HD / 4; j4++) {
            ulonglong2 w = wr[j4];
            acc2_0[2 * j4 + 0] = fma2(hk0, w.x, acc2_0[2 * j4 + 0]);
            acc2_0[2 * j4 + 1] = fma2(hk0, w.y, acc2_0[2 * j4 + 1]);
            acc2_1[2 * j4 + 0] = fma2(hk1, w.x, acc2_1[2 * j4 + 0]);
            acc2_1[2 * j4 + 1] = fma2(hk1, w.y, acc2_1[2 * j4 + 1]);
        }
    }
    float h2_0[HD], h2_1[HD];
    #pragma unroll
    for (int i = 0; i < HD / 2; i++) {
        float blo = dsm[W_OFF_B2 + 2 * i + 0];
        float bhi = dsm[W_OFF_B2 + 2 * i + 1];
        float lo, hi;
        unpack2(acc2_0[i], lo, hi);
        h2_0[2 * i + 0] = fmaxf(lo + blo + h0[2 * i + 0], 0.f);
        h2_0[2 * i + 1] = fmaxf(hi + bhi + h0[2 * i + 1], 0.f);
        unpack2(acc2_1[i], lo, hi);
        h2_1[2 * i + 0] = fmaxf(lo + blo + h1[2 * i + 0], 0.f);
        h2_1[2 * i + 1] = fmaxf(hi + bhi + h1[2 * i + 1], 0.f);
    }

    // ---- GEMM3: h2 @ W3 ----
    ull o01_0 = 0ULL, o23_0 = 0ULL, o01_1 = 0ULL, o23_1 = 0ULL;
    #pragma unroll 8
    for (int k = 0; k < HD; k++) {
        ull hk0 = pack2(h2_0[k]);
        ull hk1 = pack2(h2_1[k]);
        ulonglong2 w = *(const ulonglong2*)(dsm + W_OFF_W3 + k * EDIM);
        o01_0 = fma2(hk0, w.x, o01_0);
        o23_0 = fma2(hk0, w.y, o23_0);
        o01_1 = fma2(hk1, w.x, o01_1);
        o23_1 = fma2(hk1, w.y, o23_1);
    }

    float bo0 = dsm[W_OFF_BO + 0], bo1 = dsm[W_OFF_BO + 1];
    float bo2 = dsm[W_OFF_BO + 2], bo3 = dsm[W_OFF_BO + 3];

    float a, b;
    if (e0 < n_edges) {
        float4 r;
        unpack2(o01_0, a, b); r.x = a + cd0[0] + bo0; r.y = b + cd0[1] + bo1;
        unpack2(o23_0, a, b); r.z = a + cd0[2] + bo2; r.w = b + cd0[3] + bo3;
        ((float4*)out)[e0] = r;
    }
    if (e1 < n_edges) {
        float4 r;
        unpack2(o01_1, a, b); r.x = a + cd1[0] + bo0; r.y = b + cd1[1] + bo1;
        unpack2(o23_1, a, b); r.z = a + cd1[2] + bo2; r.w = b + cd1[3] + bo3;
        ((float4*)out)[e1] = r;
    }
}

// ---------------------------------------------------------------------------
extern "C" void kernel_launch(void* const* d_in, const int* in_sizes, int n_in,
                              void* d_out, int out_size) {
    const float* x  = (const float*)d_in[0];
    const void*  ei = d_in[1];
    const float* Wd = (const float*)d_in[2];
    const float* bd = (const float*)d_in[3];
    const float* W1 = (const float*)d_in[4];
    const float* b1 = (const float*)d_in[5];
    const float* W2 = (const float*)d_in[6];
    const float* b2 = (const float*)d_in[7];
    const float* W3 = (const float*)d_in[8];
    const float* b3 = (const float*)d_in[9];
    float* out = (float*)d_out;

    int n_nodes = in_sizes[0] / LDIM;
    if (n_nodes > NN_MAX) n_nodes = NN_MAX;
    int n_edges = in_sizes[1] / 2;

    static int attr_done = 0;
    if (!attr_done) {
        cudaFuncSetAttribute(edge_kernel,
                             cudaFuncAttributeMaxDynamicSharedMemorySize,
                             SMEM_BYTES);
        attr_done = 1;
    }

    precompute_u<<<(n_nodes + 255) / 256, 256>>>(x, W1, Wd, n_nodes);

    int edges_per_block = NWARPS * EPW;   // 512
    int blocks = (n_edges + edges_per_block - 1) / edges_per_block;
    edge_kernel<<<blocks, 256, SMEM_BYTES>>>(x, ei, W1, b1, Wd, bd,
                                             W2, b2, W3, b3, out, n_edges, n_nodes);
}

// round 9
// speedup vs baseline: 1.2489x; 1.0842x over previous
#include <cuda_runtime.h>
#include <cstdint>

typedef unsigned long long ull;

#define NN_MAX 100000
#define LDIM 64
#define HD 32
#define EDIM 4
#define NCOL 36   // 32 (W1) + 4 (W_direct) fused columns

// dynamic smem layout (float offsets)
#define W_OFF_WDIFF 0
#define W_OFF_W2    2304
#define W_OFF_W3    3328
#define W_OFF_B1    3456
#define W_OFF_B2    3488
#define W_OFF_BO    3520
#define TILE_OFF    3536
#define M_CH        20                      // chunk row stride: 16 + 4 pad (5 float4s, odd -> conflict-free)
#define EPW         64                      // edges per warp (EPT=2)
#define PER_WARP    (EPW * M_CH + EPW * NCOL)     // 1280 + 2304 = 3584
#define NWARPS      4
#define SMEM_FLOATS (TILE_OFF + NWARPS * PER_WARP)  // 3536 + 14336 = 17872
#define SMEM_BYTES  (SMEM_FLOATS * 4)               // 71488 -> 3 blocks/SM

// Scratch: u[node][j] = sum_{k<64} x[node][k] * [W1 | Wd][k][j]
__device__ __align__(16) float g_u[NN_MAX * NCOL];

__device__ __forceinline__ ull pack2(float a) {
    ull r; asm("mov.b64 %0, {%1, %1};" : "=l"(r) : "f"(a)); return r;
}
__device__ __forceinline__ ull fma2(ull a, ull b, ull c) {
    ull d; asm("fma.rn.f32x2 %0, %1, %2, %3;" : "=l"(d) : "l"(a), "l"(b), "l"(c)); return d;
}
__device__ __forceinline__ ull add2(ull a, ull b) {
    ull d; asm("add.rn.f32x2 %0, %1, %2;" : "=l"(d) : "l"(a), "l"(b)); return d;
}
__device__ __forceinline__ void unpack2(ull v, float& lo, float& hi) {
    asm("mov.b64 {%0, %1}, %2;" : "=f"(lo), "=f"(hi) : "l"(v));
}

// ---------------------------------------------------------------------------
// Kernel 1: per-node precompute u = x[:, :] @ [W1[:64] | Wd[:64]]
// ---------------------------------------------------------------------------
__global__ void __launch_bounds__(256) precompute_u(
    const float* __restrict__ x,
    const float* __restrict__ W1,
    const float* __restrict__ Wd,
    int n_nodes)
{
    __shared__ __align__(16) float sW[LDIM][NCOL];
    int tid = threadIdx.x;
    for (int i = tid; i < LDIM * NCOL; i += 256) {
        int k = i / NCOL, j = i - k * NCOL;
        sW[k][j] = (j < HD) ? W1[k * HD + j] : Wd[k * EDIM + (j - HD)];
    }
    __syncthreads();

    int node = blockIdx.x * 256 + tid;
    if (node >= n_nodes) return;

    float acc[NCOL];
    #pragma unroll
    for (int j = 0; j < NCOL; j++) acc[j] = 0.f;

    const float4* xr = (const float4*)(x + (size_t)node * LDIM);
    #pragma unroll 4
    for (int k4 = 0; k4 < LDIM / 4; k4++) {
        float4 v = __ldg(xr + k4);
        #pragma unroll
        for (int j = 0; j < NCOL; j++) {
            acc[j] = fmaf(v.x, sW[4 * k4 + 0][j], acc[j]);
            acc[j] = fmaf(v.y, sW[4 * k4 + 1][j], acc[j]);
            acc[j] = fmaf(v.z, sW[4 * k4 + 2][j], acc[j]);
            acc[j] = fmaf(v.w, sW[4 * k4 + 3][j], acc[j]);
        }
    }
    float4* ur = (float4*)(g_u + (size_t)node * NCOL);
    #pragma unroll
    for (int j4 = 0; j4 < NCOL / 4; j4++) {
        float4 r;
        r.x = acc[4 * j4 + 0]; r.y = acc[4 * j4 + 1];
        r.z = acc[4 * j4 + 2]; r.w = acc[4 * j4 + 3];
        ur[j4] = r;
    }
}

// ---------------------------------------------------------------------------
// Kernel 2: warp-cooperative edge MLP, 2 edges/thread, k-chunked m-tile.
// GEMM1 runs in 4 chunks of 16 k-values; each chunk: cooperative gather of
// max(xs,xt)[chunk] for 64 edges into a small smem tile, then partial GEMM.
// Small tiles -> 71.5 KB/block -> 3 blocks/SM (12 warps) vs 1 block before.
// ---------------------------------------------------------------------------
__global__ void __launch_bounds__(128, 3) edge_kernel(
    const float* __restrict__ x,
    const void* __restrict__ ei,
    const float* __restrict__ W1, const float* __restrict__ b1,
    const float* __restrict__ Wd, const float* __restrict__ bd,
    const float* __restrict__ W2, const float* __restrict__ b2,
    const float* __restrict__ W3, const float* __restrict__ b3,
    float* __restrict__ out, int n_edges, int n_nodes)
{
    extern __shared__ __align__(16) float dsm[];
    __shared__ int s_is64;

    int tid = threadIdx.x;
    if (tid == 0) {
        // dtype probe: int32 data read as int64 pairs gives values far outside
        // [0, n_nodes). Deterministic, identical in every block.
        const long long* p = (const long long*)ei;
        int ok = 1;
        for (int i = 0; i < 64; i++) {
            long long v = p[i];
            if (v < 0 || v >= n_nodes) { ok = 0; break; }
        }
        s_is64 = ok;
    }
    // weights -> dynamic smem
    for (int i = tid; i < LDIM * NCOL; i += 128) {
        int k = i / NCOL, j = i - k * NCOL;
        float hi, lo;
        if (j < HD) { hi = W1[(LDIM + k) * HD + j];        lo = W1[k * HD + j]; }
        else        { hi = Wd[(LDIM + k) * EDIM + (j-HD)]; lo = Wd[k * EDIM + (j-HD)]; }
        dsm[W_OFF_WDIFF + i] = hi - lo;
    }
    for (int i = tid; i < HD * HD; i += 128)   dsm[W_OFF_W2 + i] = W2[i];
    for (int i = tid; i < HD * EDIM; i += 128) dsm[W_OFF_W3 + i] = W3[i];
    if (tid < HD)  { dsm[W_OFF_B1 + tid] = b1[tid]; dsm[W_OFF_B2 + tid] = b2[tid]; }
    if (tid < EDIM) dsm[W_OFF_BO + tid] = b3[tid] + bd[tid];
    __syncthreads();

    int warp = tid >> 5, lane = tid & 31;
    int tile_base = (blockIdx.x * NWARPS + warp) * EPW;
    if (tile_base >= n_edges) return;

    int e0 = tile_base + lane;
    int e1 = e0 + 32;
    int ec0 = (e0 < n_edges) ? e0 : (n_edges - 1);
    int ec1 = (e1 < n_edges) ? e1 : (n_edges - 1);

    // ---- index loads: dtype-flexible, clamped (never IMA) ----
    unsigned s0, t0, s1, t1;
    if (s_is64) {
        s0 = (unsigned)((const long long*)ei)[ec0];
        t0 = (unsigned)((const long long*)ei)[(size_t)n_edges + ec0];
        s1 = (unsigned)((const long long*)ei)[ec1];
        t1 = (unsigned)((const long long*)ei)[(size_t)n_edges + ec1];
    } else {
        s0 = (unsigned)((const int*)ei)[ec0];
        t0 = (unsigned)((const int*)ei)[(size_t)n_edges + ec0];
        s1 = (unsigned)((const int*)ei)[ec1];
        t1 = (unsigned)((const int*)ei)[(size_t)n_edges + ec1];
    }
    unsigned nm1 = (unsigned)(n_nodes - 1);
    s0 = (s0 < nm1) ? s0 : nm1;  t0 = (t0 < nm1) ? t0 : nm1;
    s1 = (s1 < nm1) ? s1 : nm1;  t1 = (t1 < nm1) ? t1 : nm1;

    float* sm_m = dsm + TILE_OFF + warp * PER_WARP;   // [64][M_CH] chunk tile
    float* sm_u = sm_m + EPW * M_CH;                  // [64][NCOL]

    const unsigned FULL = 0xffffffffu;
    int half  = lane >> 4;        // 0 = s-row, 1 = t-row
    int li    = lane & 15;
    int esub4 = li >> 2;          // edge-within-pass (0..3)
    int f     = lane & 3;         // float4-within-chunk (0..3)

    // ---- u gather (once): lanes 0-8 cover 36 floats of u[s], 16-24 u[t] ----
    #pragma unroll 4
    for (int ee = 0; ee < EPW; ee++) {
        unsigned ssel = (ee < 32) ? s0 : s1;
        unsigned tsel = (ee < 32) ? t0 : t1;
        unsigned sr = __shfl_sync(FULL, ssel, ee & 31);
        unsigned tr = __shfl_sync(FULL, tsel, ee & 31);
        unsigned row = half ? tr : sr;
        const float4* pu = (const float4*)(g_u + (size_t)row * NCOL);
        int uli = (li < 9) ? li : 8;
        float4 uv = __ldg(pu + uli);
        float4 us;
        us.x = uv.x + __shfl_xor_sync(FULL, uv.x, 16);
        us.y = uv.y + __shfl_xor_sync(FULL, uv.y, 16);
        us.z = uv.z + __shfl_xor_sync(FULL, uv.z, 16);
        us.w = uv.w + __shfl_xor_sync(FULL, uv.w, 16);
        if (lane < 9) *(float4*)(sm_u + ee * NCOL + li * 4) = us;
    }

    // ================= GEMM1 in 4 k-chunks of 16 =================
    ull acc0[NCOL / 2], acc1[NCOL / 2];
    #pragma unroll
    for (int i = 0; i < NCOL / 2; i++) { acc0[i] = 0ULL; acc1[i] = 0ULL; }

    #pragma unroll 1
    for (int c = 0; c < 4; c++) {
        __syncwarp();
        // gather chunk c: 16 passes x 4 edges; lanes 0-15 s-rows, 16-31 t-rows
        #pragma unroll 4
        for (int pass = 0; pass < 16; pass++) {
            int ee = pass * 4 + esub4;
            unsigned ssel = (pass < 8) ? s0 : s1;
            unsigned tsel = (pass < 8) ? t0 : t1;
            unsigned sr = __shfl_sync(FULL, ssel, ee & 31);
            unsigned tr = __shfl_sync(FULL, tsel, ee & 31);
            unsigned row = half ? tr : sr;
            const float4* px = (const float4*)(x + (size_t)row * LDIM + c * 16);
            float4 v = __ldg(px + f);
            float4 m;
            m.x = fmaxf(v.x, __shfl_xor_sync(FULL, v.x, 16));
            m.y = fmaxf(v.y, __shfl_xor_sync(FULL, v.y, 16));
            m.z = fmaxf(v.z, __shfl_xor_sync(FULL, v.z, 16));
            m.w = fmaxf(v.w, __shfl_xor_sync(FULL, v.w, 16));
            if (lane < 16) *(float4*)(sm_m + ee * M_CH + f * 4) = m;
        }
        __syncwarp();
        // partial GEMM over this chunk's 16 k-values, both edges
        #pragma unroll
        for (int k4 = 0; k4 < 4; k4++) {
            float4 mv0 = *(const float4*)(sm_m + lane * M_CH + k4 * 4);
            float4 mv1 = *(const float4*)(sm_m + (lane + 32) * M_CH + k4 * 4);
            float a4[4] = {mv0.x, mv0.y, mv0.z, mv0.w};
            float b4[4] = {mv1.x, mv1.y, mv1.z, mv1.w};
            #pragma unroll
            for (int kk = 0; kk < 4; kk++) {
                ull ma = pack2(a4[kk]);
                ull mb = pack2(b4[kk]);
                const ulonglong2* wr = (const ulonglong2*)
                    (dsm + W_OFF_WDIFF + (c * 16 + k4 * 4 + kk) * NCOL);
                #pragma unroll
                for (int j4 = 0; j4 < NCOL / 4; j4++) {
                    ulonglong2 w = wr[j4];
                    acc0[2 * j4 + 0] = fma2(ma, w.x, acc0[2 * j4 + 0]);
                    acc0[2 * j4 + 1] = fma2(ma, w.y, acc0[2 * j4 + 1]);
                    acc1[2 * j4 + 0] = fma2(mb, w.x, acc1[2 * j4 + 0]);
                    acc1[2 * j4 + 1] = fma2(mb, w.y, acc1[2 * j4 + 1]);
                }
            }
        }
    }

    // add presummed u_s + u_t
    const ulonglong2* uu0 = (const ulonglong2*)(sm_u + lane * NCOL);
    const ulonglong2* uu1 = (const ulonglong2*)(sm_u + (lane + 32) * NCOL);
    #pragma unroll
    for (int j4 = 0; j4 < NCOL / 4; j4++) {
        ulonglong2 w0 = uu0[j4];
        ulonglong2 w1 = uu1[j4];
        acc0[2 * j4 + 0] = add2(acc0[2 * j4 + 0], w0.x);
        acc0[2 * j4 + 1] = add2(acc0[2 * j4 + 1], w0.y);
        acc1[2 * j4 + 0] = add2(acc1[2 * j4 + 0], w1.x);
        acc1[2 * j4 + 1] = add2(acc1[2 * j4 + 1], w1.y);
    }

    // unpack -> h (bias+relu fused) and cd (direct path, cols 32..35)
    float h0[HD], h1[HD], cd0[EDIM], cd1[EDIM];
    #pragma unroll
    for (int i = 0; i < HD / 2; i++) {
        float blo = dsm[W_OFF_B1 + 2 * i + 0];
        float bhi = dsm[W_OFF_B1 + 2 * i + 1];
        float lo, hi;
        unpack2(acc0[i], lo, hi);
        h0[2 * i + 0] = fmaxf(lo + blo, 0.f);
        h0[2 * i + 1] = fmaxf(hi + bhi, 0.f);
        unpack2(acc1[i], lo, hi);
        h1[2 * i + 0] = fmaxf(lo + blo, 0.f);
        h1[2 * i + 1] = fmaxf(hi + bhi, 0.f);
    }
    unpack2(acc0[16], cd0[0], cd0[1]);
    unpack2(acc0[17], cd0[2], cd0[3]);
    unpack2(acc1[16], cd1[0], cd1[1]);
    unpack2(acc1[17], cd1[2], cd1[3]);

    // ---- GEMM2: h @ W2, residual + relu ----
    ull acc2_0[HD / 2], acc2_1[HD / 2];
    #pragma unroll
    for (int i = 0; i < HD / 2; i++) { acc2_0[i] = 0ULL; acc2_1[i] = 0ULL; }
    #pragma unroll 8
    for (int k = 0; k < HD; k++) {
        ull hk0 = pack2(h0[k]);
        ull hk1 = pack2(h1[k]);
        const ulonglong2* wr = (const ulonglong2*)(dsm + W_OFF_W2 + k * HD);
        #pragma unroll
        for (int j4 = 0; j4 < HD / 4; j4++) {
            ulonglong2 w = wr[j4];
            acc2_0[2 * j4 + 0] = fma2(hk0, w.x, acc2_0[2 * j4 + 0]);
            acc2_0[2 * j4 + 1] = fma2(hk0, w.y, acc2_0[2 * j4 + 1]);
            acc2_1[2 * j4 + 0] = fma2(hk1, w.x, acc2_1[2 * j4 + 0]);
            acc2_1[2 * j4 + 1] = fma2(hk1, w.y, acc2_1[2 * j4 + 1]);
        }
    }
    float h2_0[HD], h2_1[HD];
    #pragma unroll
    for (int i = 0; i < HD / 2; i++) {
        float blo = dsm[W_OFF_B2 + 2 * i + 0];
        float bhi = dsm[W_OFF_B2 + 2 * i + 1];
        float lo, hi;
        unpack2(acc2_0[i], lo, hi);
        h2_0[2 * i + 0] = fmaxf(lo + blo + h0[2 * i + 0], 0.f);
        h2_0[2 * i + 1] = fmaxf(hi + bhi + h0[2 * i + 1], 0.f);
        unpack2(acc2_1[i], lo, hi);
        h2_1[2 * i + 0] = fmaxf(lo + blo + h1[2 * i + 0], 0.f);
        h2_1[2 * i + 1] = fmaxf(hi + bhi + h1[2 * i + 1], 0.f);
    }

    // ---- GEMM3: h2 @ W3 ----
    ull o01_0 = 0ULL, o23_0 = 0ULL, o01_1 = 0ULL, o23_1 = 0ULL;
    #pragma unroll 8
    for (int k = 0; k < HD; k++) {
        ull hk0 = pack2(h2_0[k]);
        ull hk1 = pack2(h2_1[k]);
        ulonglong2 w = *(const ulonglong2*)(dsm + W_OFF_W3 + k * EDIM);
        o01_0 = fma2(hk0, w.x, o01_0);
        o23_0 = fma2(hk0, w.y, o23_0);
        o01_1 = fma2(hk1, w.x, o01_1);
        o23_1 = fma2(hk1, w.y, o23_1);
    }

    float bo0 = dsm[W_OFF_BO + 0], bo1 = dsm[W_OFF_BO + 1];
    float bo2 = dsm[W_OFF_BO + 2], bo3 = dsm[W_OFF_BO + 3];

    float a, b;
    if (e0 < n_edges) {
        float4 r;
        unpack2(o01_0, a, b); r.x = a + cd0[0] + bo0; r.y = b + cd0[1] + bo1;
        unpack2(o23_0, a, b); r.z = a + cd0[2] + bo2; r.w = b + cd0[3] + bo3;
        ((float4*)out)[e0] = r;
    }
    if (e1 < n_edges) {
        float4 r;
        unpack2(o01_1, a, b); r.x = a + cd1[0] + bo0; r.y = b + cd1[1] + bo1;
        unpack2(o23_1, a, b); r.z = a + cd1[2] + bo2; r.w = b + cd1[3] + bo3;
        ((float4*)out)[e1] = r;
    }
}

// ---------------------------------------------------------------------------
extern "C" void kernel_launch(void* const* d_in, const int* in_sizes, int n_in,
                              void* d_out, int out_size) {
    const float* x  = (const float*)d_in[0];
    const void*  ei = d_in[1];
    const float* Wd = (const float*)d_in[2];
    const float* bd = (const float*)d_in[3];
    const float* W1 = (const float*)d_in[4];
    const float* b1 = (const float*)d_in[5];
    const float* W2 = (const float*)d_in[6];
    const float* b2 = (const float*)d_in[7];
    const float* W3 = (const float*)d_in[8];
    const float* b3 = (const float*)d_in[9];
    float* out = (float*)d_out;

    int n_nodes = in_sizes[0] / LDIM;
    if (n_nodes > NN_MAX) n_nodes = NN_MAX;
    int n_edges = in_sizes[1] / 2;

    static int attr_done = 0;
    if (!attr_done) {
        cudaFuncSetAttribute(edge_kernel,
                             cudaFuncAttributeMaxDynamicSharedMemorySize,
                             SMEM_BYTES);
        attr_done = 1;
    }

    precompute_u<<<(n_nodes + 255) / 256, 256>>>(x, W1, Wd, n_nodes);

    int edges_per_block = NWARPS * EPW;   // 256
    int blocks = (n_edges + edges_per_block - 1) / edges_per_block;
    edge_kernel<<<blocks, 128, SMEM_BYTES>>>(x, ei, W1, b1, Wd, bd,
                                             W2, b2, W3, b3, out, n_edges, n_nodes);
}

// round 10
// speedup vs baseline: 1.2809x; 1.0257x over previous
#include <cuda_runtime.h>
#include <cstdint>

typedef unsigned long long ull;

#define NN_MAX 100000
#define LDIM 64
#define HD 32
#define EDIM 4
#define NCOL 36   // 32 (W1) + 4 (W_direct) fused columns

// dynamic smem layout (float offsets)
#define W_OFF_WDIFF 0
#define W_OFF_W2    2304
#define W_OFF_W3    3328
#define W_OFF_B1    3456
#define W_OFF_B2    3488
#define W_OFF_BO    3520
#define FLAG_OFF    3524
#define TILE_OFF    3528                    // 16B aligned (3528*4 = 14112)
#define M_CH        20                      // chunk row stride: 16 + 4 pad (5 float4s, odd -> conflict-free)
#define EPW         64                      // edges per warp (EPT=2)
// m-chunk tile (64*20=1280 fl) and u tile (64*36=2304 fl) are NOT live at the
// same time -> alias them in one 2304-float buffer per warp.
#define PER_WARP    2304
#define NWARPS      4
#define SMEM_FLOATS (TILE_OFF + NWARPS * PER_WARP)  // 3528 + 9216 = 12744
#define SMEM_BYTES  (SMEM_FLOATS * 4)               // 50976 -> 4 blocks/SM

// Scratch: u[node][j] = sum_{k<64} x[node][k] * [W1 | Wd][k][j]
__device__ __align__(16) float g_u[NN_MAX * NCOL];

__device__ __forceinline__ ull pack2(float a) {
    ull r; asm("mov.b64 %0, {%1, %1};" : "=l"(r) : "f"(a)); return r;
}
__device__ __forceinline__ ull fma2(ull a, ull b, ull c) {
    ull d; asm("fma.rn.f32x2 %0, %1, %2, %3;" : "=l"(d) : "l"(a), "l"(b), "l"(c)); return d;
}
__device__ __forceinline__ ull add2(ull a, ull b) {
    ull d; asm("add.rn.f32x2 %0, %1, %2;" : "=l"(d) : "l"(a), "l"(b)); return d;
}
__device__ __forceinline__ void unpack2(ull v, float& lo, float& hi) {
    asm("mov.b64 {%0, %1}, %2;" : "=f"(lo), "=f"(hi) : "l"(v));
}

// ---------------------------------------------------------------------------
// Kernel 1: per-node precompute u = x[:, :] @ [W1[:64] | Wd[:64]]
// ---------------------------------------------------------------------------
__global__ void __launch_bounds__(256) precompute_u(
    const float* __restrict__ x,
    const float* __restrict__ W1,
    const float* __restrict__ Wd,
    int n_nodes)
{
    __shared__ __align__(16) float sW[LDIM][NCOL];
    int tid = threadIdx.x;
    for (int i = tid; i < LDIM * NCOL; i += 256) {
        int k = i / NCOL, j = i - k * NCOL;
        sW[k][j] = (j < HD) ? W1[k * HD + j] : Wd[k * EDIM + (j - HD)];
    }
    __syncthreads();

    int node = blockIdx.x * 256 + tid;
    if (node >= n_nodes) return;

    float acc[NCOL];
    #pragma unroll
    for (int j = 0; j < NCOL; j++) acc[j] = 0.f;

    const float4* xr = (const float4*)(x + (size_t)node * LDIM);
    #pragma unroll 4
    for (int k4 = 0; k4 < LDIM / 4; k4++) {
        float4 v = __ldg(xr + k4);
        #pragma unroll
        for (int j = 0; j < NCOL; j++) {
            acc[j] = fmaf(v.x, sW[4 * k4 + 0][j], acc[j]);
            acc[j] = fmaf(v.y, sW[4 * k4 + 1][j], acc[j]);
            acc[j] = fmaf(v.z, sW[4 * k4 + 2][j], acc[j]);
            acc[j] = fmaf(v.w, sW[4 * k4 + 3][j], acc[j]);
        }
    }
    float4* ur = (float4*)(g_u + (size_t)node * NCOL);
    #pragma unroll
    for (int j4 = 0; j4 < NCOL / 4; j4++) {
        float4 r;
        r.x = acc[4 * j4 + 0]; r.y = acc[4 * j4 + 1];
        r.z = acc[4 * j4 + 2]; r.w = acc[4 * j4 + 3];
        ur[j4] = r;
    }
}

// ---------------------------------------------------------------------------
// Sequential tail: bias+relu -> GEMM2 (residual) -> GEMM3 -> store, one edge.
// Inlined; array indexed only by compile-time constants -> stays in registers.
// ---------------------------------------------------------------------------
__device__ __forceinline__ void tail_edge(
    const ull (&acc)[NCOL / 2], const float* __restrict__ dsm,
    float* __restrict__ out, int e, int n_edges)
{
    if (e >= n_edges) return;

    float h[HD], cd[EDIM];
    #pragma unroll
    for (int i = 0; i < HD / 2; i++) {
        float lo, hi; unpack2(acc[i], lo, hi);
        h[2 * i + 0] = fmaxf(lo + dsm[W_OFF_B1 + 2 * i + 0], 0.f);
        h[2 * i + 1] = fmaxf(hi + dsm[W_OFF_B1 + 2 * i + 1], 0.f);
    }
    unpack2(acc[16], cd[0], cd[1]);
    unpack2(acc[17], cd[2], cd[3]);

    // GEMM2: h @ W2
    ull acc2[HD / 2];
    #pragma unroll
    for (int i = 0; i < HD / 2; i++) acc2[i] = 0ULL;
    #pragma unroll 8
    for (int k = 0; k < HD; k++) {
        ull hk = pack2(h[k]);
        const ulonglong2* wr = (const ulonglong2*)(dsm + W_OFF_W2 + k * HD);
        #pragma unroll
        for (int j4 = 0; j4 < HD / 4; j4++) {
            ulonglong2 w = wr[j4];
            acc2[2 * j4 + 0] = fma2(hk, w.x, acc2[2 * j4 + 0]);
            acc2[2 * j4 + 1] = fma2(hk, w.y, acc2[2 * j4 + 1]);
        }
    }
    // residual + relu, h <- h2 (h[j] only read by its own j -> safe reuse)
    #pragma unroll
    for (int i = 0; i < HD / 2; i++) {
        float lo, hi; unpack2(acc2[i], lo, hi);
        h[2 * i + 0] = fmaxf(lo + dsm[W_OFF_B2 + 2 * i + 0] + h[2 * i + 0], 0.f);
        h[2 * i + 1] = fmaxf(hi + dsm[W_OFF_B2 + 2 * i + 1] + h[2 * i + 1], 0.f);
    }

    // GEMM3: h2 @ W3
    ull o01 = 0ULL, o23 = 0ULL;
    #pragma unroll 8
    for (int k = 0; k < HD; k++) {
        ull hk = pack2(h[k]);
        ulonglong2 w = *(const ulonglong2*)(dsm + W_OFF_W3 + k * EDIM);
        o01 = fma2(hk, w.x, o01);
        o23 = fma2(hk, w.y, o23);
    }
    float a, b;
    float4 r;
    unpack2(o01, a, b);
    r.x = a + cd[0] + dsm[W_OFF_BO + 0];
    r.y = b + cd[1] + dsm[W_OFF_BO + 1];
    unpack2(o23, a, b);
    r.z = a + cd[2] + dsm[W_OFF_BO + 2];
    r.w = b + cd[3] + dsm[W_OFF_BO + 3];
    ((float4*)out)[e] = r;
}

// ---------------------------------------------------------------------------
// Kernel 2: warp-cooperative edge MLP, 2 edges/thread, k-chunked m-tile,
// m/u tiles aliased, sequential per-edge tail. 51 KB smem + <=128 regs
// -> 4 blocks/SM (16 warps).
// ---------------------------------------------------------------------------
__global__ void __launch_bounds__(128, 4) edge_kernel(
    const float* __restrict__ x,
    const void* __restrict__ ei,
    const float* __restrict__ W1, const float* __restrict__ b1,
    const float* __restrict__ Wd, const float* __restrict__ bd,
    const float* __restrict__ W2, const float* __restrict__ b2,
    const float* __restrict__ W3, const float* __restrict__ b3,
    float* __restrict__ out, int n_edges, int n_nodes)
{
    extern __shared__ __align__(16) float dsm[];

    int tid = threadIdx.x;
    if (tid == 0) {
        // dtype probe: int32 data read as int64 pairs gives values far outside
        // [0, n_nodes). Deterministic, identical in every block.
        const long long* p = (const long long*)ei;
        int ok = 1;
        for (int i = 0; i < 64; i++) {
            long long v = p[i];
            if (v < 0 || v >= n_nodes) { ok = 0; break; }
        }
        ((int*)dsm)[FLAG_OFF] = ok;
    }
    // weights -> dynamic smem
    for (int i = tid; i < LDIM * NCOL; i += 128) {
        int k = i / NCOL, j = i - k * NCOL;
        float hi, lo;
        if (j < HD) { hi = W1[(LDIM + k) * HD + j];        lo = W1[k * HD + j]; }
        else        { hi = Wd[(LDIM + k) * EDIM + (j-HD)]; lo = Wd[k * EDIM + (j-HD)]; }
        dsm[W_OFF_WDIFF + i] = hi - lo;
    }
    for (int i = tid; i < HD * HD; i += 128)   dsm[W_OFF_W2 + i] = W2[i];
    for (int i = tid; i < HD * EDIM; i += 128) dsm[W_OFF_W3 + i] = W3[i];
    if (tid < HD)  { dsm[W_OFF_B1 + tid] = b1[tid]; dsm[W_OFF_B2 + tid] = b2[tid]; }
    if (tid < EDIM) dsm[W_OFF_BO + tid] = b3[tid] + bd[tid];
    __syncthreads();
    int s_is64 = ((const int*)dsm)[FLAG_OFF];

    int warp = tid >> 5, lane = tid & 31;
    int tile_base = (blockIdx.x * NWARPS + warp) * EPW;
    if (tile_base >= n_edges) return;

    int e0 = tile_base + lane;
    int e1 = e0 + 32;
    int ec0 = (e0 < n_edges) ? e0 : (n_edges - 1);
    int ec1 = (e1 < n_edges) ? e1 : (n_edges - 1);

    // ---- index loads: dtype-flexible, clamped (never IMA) ----
    unsigned s0, t0, s1, t1;
    if (s_is64) {
        s0 = (unsigned)((const long long*)ei)[ec0];
        t0 = (unsigned)((const long long*)ei)[(size_t)n_edges + ec0];
        s1 = (unsigned)((const long long*)ei)[ec1];
        t1 = (unsigned)((const long long*)ei)[(size_t)n_edges + ec1];
    } else {
        s0 = (unsigned)((const int*)ei)[ec0];
        t0 = (unsigned)((const int*)ei)[(size_t)n_edges + ec0];
        s1 = (unsigned)((const int*)ei)[ec1];
        t1 = (unsigned)((const int*)ei)[(size_t)n_edges + ec1];
    }
    unsigned nm1 = (unsigned)(n_nodes - 1);
    s0 = (s0 < nm1) ? s0 : nm1;  t0 = (t0 < nm1) ? t0 : nm1;
    s1 = (s1 < nm1) ? s1 : nm1;  t1 = (t1 < nm1) ? t1 : nm1;

    float* sm_m = dsm + TILE_OFF + warp * PER_WARP;   // [64][M_CH] chunk tile
    float* sm_u = sm_m;                               // [64][NCOL], aliased (post-GEMM1)

    const unsigned FULL = 0xffffffffu;
    int half  = lane >> 4;        // 0 = s-row, 1 = t-row
    int li    = lane & 15;
    int esub4 = li >> 2;          // edge-within-pass (0..3)
    int f     = lane & 3;         // float4-within-chunk (0..3)

    // ================= GEMM1 in 4 k-chunks of 16 =================
    ull acc0[NCOL / 2], acc1[NCOL / 2];
    #pragma unroll
    for (int i = 0; i < NCOL / 2; i++) { acc0[i] = 0ULL; acc1[i] = 0ULL; }

    #pragma unroll 1
    for (int c = 0; c < 4; c++) {
        __syncwarp();
        // gather chunk c: 16 passes x 4 edges; lanes 0-15 s-rows, 16-31 t-rows
        #pragma unroll 4
        for (int pass = 0; pass < 16; pass++) {
            int ee = pass * 4 + esub4;
            unsigned ssel = (pass < 8) ? s0 : s1;
            unsigned tsel = (pass < 8) ? t0 : t1;
            unsigned sr = __shfl_sync(FULL, ssel, ee & 31);
            unsigned tr = __shfl_sync(FULL, tsel, ee & 31);
            unsigned row = half ? tr : sr;
            const float4* px = (const float4*)(x + (size_t)row * LDIM + c * 16);
            float4 v = __ldg(px + f);
            float4 m;
            m.x = fmaxf(v.x, __shfl_xor_sync(FULL, v.x, 16));
            m.y = fmaxf(v.y, __shfl_xor_sync(FULL, v.y, 16));
            m.z = fmaxf(v.z, __shfl_xor_sync(FULL, v.z, 16));
            m.w = fmaxf(v.w, __shfl_xor_sync(FULL, v.w, 16));
            if (lane < 16) *(float4*)(sm_m + ee * M_CH + f * 4) = m;
        }
        __syncwarp();
        // partial GEMM over this chunk's 16 k-values, both edges
        #pragma unroll
        for (int k4 = 0; k4 < 4; k4++) {
            float4 mv0 = *(const float4*)(sm_m + lane * M_CH + k4 * 4);
            float4 mv1 = *(const float4*)(sm_m + (lane + 32) * M_CH + k4 * 4);
            float a4[4] = {mv0.x, mv0.y, mv0.z, mv0.w};
            float b4[4] = {mv1.x, mv1.y, mv1.z, mv1.w};
            #pragma unroll
            for (int kk = 0; kk < 4; kk++) {
                ull ma = pack2(a4[kk]);
                ull mb = pack2(b4[kk]);
                const ulonglong2* wr = (const ulonglong2*)
                    (dsm + W_OFF_WDIFF + (c * 16 + k4 * 4 + kk) * NCOL);
                #pragma unroll
                for (int j4 = 0; j4 < NCOL / 4; j4++) {
                    ulonglong2 w = wr[j4];
                    acc0[2 * j4 + 0] = fma2(ma, w.x, acc0[2 * j4 + 0]);
                    acc0[2 * j4 + 1] = fma2(ma, w.y, acc0[2 * j4 + 1]);
                    acc1[2 * j4 + 0] = fma2(mb, w.x, acc1[2 * j4 + 0]);
                    acc1[2 * j4 + 1] = fma2(mb, w.y, acc1[2 * j4 + 1]);
                }
            }
        }
    }

    // ---- u gather into the (now dead) m-tile buffer ----
    __syncwarp();
    #pragma unroll 4
    for (int ee = 0; ee < EPW; ee++) {
        unsigned ssel = (ee < 32) ? s0 : s1;
        unsigned tsel = (ee < 32) ? t0 : t1;
        unsigned sr = __shfl_sync(FULL, ssel, ee & 31);
        unsigned tr = __shfl_sync(FULL, tsel, ee & 31);
        unsigned row = half ? tr : sr;
        const float4* pu = (const float4*)(g_u + (size_t)row * NCOL);
        int uli = (li < 9) ? li : 8;
        float4 uv = __ldg(pu + uli);
        float4 us;
        us.x = uv.x + __shfl_xor_sync(FULL, uv.x, 16);
        us.y = uv.y + __shfl_xor_sync(FULL, uv.y, 16);
        us.z = uv.z + __shfl_xor_sync(FULL, uv.z, 16);
        us.w = uv.w + __shfl_xor_sync(FULL, uv.w, 16);
        if (lane < 9) *(float4*)(sm_u + ee * NCOL + li * 4) = us;
    }
    __syncwarp();

    // add presummed u_s + u_t
    const ulonglong2* uu0 = (const ulonglong2*)(sm_u + lane * NCOL);
    const ulonglong2* uu1 = (const ulonglong2*)(sm_u + (lane + 32) * NCOL);
    #pragma unroll
    for (int j4 = 0; j4 < NCOL / 4; j4++) {
        ulonglong2 w0 = uu0[j4];
        ulonglong2 w1 = uu1[j4];
        acc0[2 * j4 + 0] = add2(acc0[2 * j4 + 0], w0.x);
        acc0[2 * j4 + 1] = add2(acc0[2 * j4 + 1], w0.y);
        acc1[2 * j4 + 0] = add2(acc1[2 * j4 + 0], w1.x);
        acc1[2 * j4 + 1] = add2(acc1[2 * j4 + 1], w1.y);
    }

    // ---- sequential per-edge tails (halves peak register pressure) ----
    tail_edge(acc0, dsm, out, e0, n_edges);
    tail_edge(acc1, dsm, out, e1, n_edges);
}

// ---------------------------------------------------------------------------
extern "C" void kernel_launch(void* const* d_in, const int* in_sizes, int n_in,
                              void* d_out, int out_size) {
    const float* x  = (const float*)d_in[0];
    const void*  ei = d_in[1];
    const float* Wd = (const float*)d_in[2];
    const float* bd = (const float*)d_in[3];
    const float* W1 = (const float*)d_in[4];
    const float* b1 = (const float*)d_in[5];
    const float* W2 = (const float*)d_in[6];
    const float* b2 = (const float*)d_in[7];
    const float* W3 = (const float*)d_in[8];
    const float* b3 = (const float*)d_in[9];
    float* out = (float*)d_out;

    int n_nodes = in_sizes[0] / LDIM;
    if (n_nodes > NN_MAX) n_nodes = NN_MAX;
    int n_edges = in_sizes[1] / 2;

    static int attr_done = 0;
    if (!attr_done) {
        cudaFuncSetAttribute(edge_kernel,
                             cudaFuncAttributeMaxDynamicSharedMemorySize,
                             SMEM_BYTES);
        attr_done = 1;
    }

    precompute_u<<<(n_nodes + 255) / 256, 256>>>(x, W1, Wd, n_nodes);

    int edges_per_block = NWARPS * EPW;   // 256
    int blocks = (n_edges + edges_per_block - 1) / edges_per_block;
    edge_kernel<<<blocks, 128, SMEM_BYTES>>>(x, ei, W1, b1, Wd, bd,
                                             W2, b2, W3, b3, out, n_edges, n_nodes);
}